// round 2
// baseline (speedup 1.0000x reference)
#include <cuda_runtime.h>
#include <stdint.h>

#define N    1024
#define NM1  1023
#define STEPS 32
#define TTOT 1900.0f
#define T0   1880.0f

// fp64 compile-time fold, then cast to fp32 — matches python float64 constant folding
#define C_FD ((float)(1e-16 * (910.0 * 9.81) * (910.0 * 9.81) * (910.0 * 9.81)))

// Scratch state (device globals — no allocations allowed)
__device__ float        g_Hbuf[N * N];          // ping-pong partner of d_out
__device__ float        g_D[NM1 * NM1];         // staggered diffusivity
__device__ unsigned int g_maxD[STEPS];          // per-step max(D) as ordered uint bits
__device__ float        g_t[STEPS + 1];         // simulated time per step

// ---------------------------------------------------------------------------
__global__ void init_kernel(const float* __restrict__ Hinit, float* __restrict__ H0) {
    int idx = blockIdx.x * blockDim.x + threadIdx.x;
    int stride = gridDim.x * blockDim.x;
    for (int i = idx; i < N * N; i += stride) H0[i] = Hinit[i];
    if (idx < STEPS) g_maxD[idx] = 0u;
    if (idx == STEPS) g_t[0] = T0;
}

// ---------------------------------------------------------------------------
// Kernel A: compute D on the (N-1)x(N-1) staggered grid, store it, and
// reduce max(D) into g_maxD[s]. D >= EPS > 0, so float bits order as uint.
__global__ void diffus_kernel(const float* __restrict__ H,
                              const float* __restrict__ Ztopo, int s) {
    __shared__ unsigned int smax;
    if (threadIdx.x == 0 && threadIdx.y == 0) smax = 0u;
    __syncthreads();

    int c = blockIdx.x * blockDim.x + threadIdx.x;
    int r = blockIdx.y * blockDim.y + threadIdx.y;

    float d = 0.0f;
    if (r < NM1 && c < NM1) {
        int i00 = r * N + c;
        float h00 = H[i00],     h01 = H[i00 + 1];
        float h10 = H[i00 + N], h11 = H[i00 + N + 1];
        float z00 = Ztopo[i00]     + h00, z01 = Ztopo[i00 + 1]     + h01;
        float z10 = Ztopo[i00 + N] + h10, z11 = Ztopo[i00 + N + 1] + h11;

        float havg = 0.25f * (h00 + h11 + h01 + h10);
        float sx = 0.5f * ((z01 - z00) / 100.0f + (z11 - z10) / 100.0f);
        float sy = 0.5f * ((z10 - z00) / 100.0f + (z11 - z01) / 100.0f);
        float sn = sqrtf(sx * sx + sy * sy + 1e-20f);
        float h2 = havg * havg;
        float h5 = h2 * h2 * havg;
        d = C_FD * h5 * (sn * sn) + 1e-20f;
        g_D[r * NM1 + c] = d;
    }

    atomicMax(&smax, __float_as_uint(d));
    __syncthreads();
    if (threadIdx.x == 0 && threadIdx.y == 0)
        atomicMax(&g_maxD[s], smax);
}

// ---------------------------------------------------------------------------
// Kernel B: each thread derives dt from g_maxD[s] and g_t[s] (deterministic,
// redundant but cheap), updates H, writes ping-pong buffer. One thread
// advances g_t[s+1].
__global__ void update_kernel(const float* __restrict__ Hc,
                              float* __restrict__ Hn,
                              const float* __restrict__ Ztopo,
                              const float* __restrict__ Zela, int s) {
    int c = blockIdx.x * blockDim.x + threadIdx.x;
    int r = blockIdx.y * blockDim.y + threadIdx.y;
    if (r >= N || c >= N) return;

    float maxD = __uint_as_float(g_maxD[s]);
    float t = g_t[s];
    float dt = fminf(10000.0f / (2.7f * maxD), 1.0f);
    if (!(t < TTOT)) dt = 0.0f;

    if (r == 0 && c == 0) g_t[s + 1] = t + dt;

    int idx = r * N + c;
    float h = Hc[idx];
    float hn;

    if (r > 0 && r < N - 1 && c > 0 && c < N - 1) {
        // 4 surrounding staggered D cells
        float Dul = g_D[(r - 1) * NM1 + (c - 1)];
        float Dur = g_D[(r - 1) * NM1 + c];
        float Dll = g_D[r * NM1 + (c - 1)];
        float Dlr = g_D[r * NM1 + c];

        float zc = Ztopo[idx] + h;
        float zl = Ztopo[idx - 1] + Hc[idx - 1];
        float zr = Ztopo[idx + 1] + Hc[idx + 1];
        float zu = Ztopo[idx - N] + Hc[idx - N];
        float zd = Ztopo[idx + N] + Hc[idx + N];

        float qxL = -(0.5f * (Dul + Dll)) * (zc - zl) / 100.0f;
        float qxR = -(0.5f * (Dur + Dlr)) * (zr - zc) / 100.0f;
        float qyU = -(0.5f * (Dul + Dur)) * (zc - zu) / 100.0f;
        float qyD = -(0.5f * (Dll + Dlr)) * (zd - zc) / 100.0f;

        float dHdt = -((qxR - qxL) / 100.0f + (qyD - qyU) / 100.0f);
        float b = fminf(1e-3f * (zc - Zela[idx]), 0.3f);
        hn = fmaxf(h + dt * (dHdt + b), 0.0f);
    } else {
        hn = fmaxf(h, 0.0f);
    }
    Hn[idx] = hn;
}

// ---------------------------------------------------------------------------
extern "C" void kernel_launch(void* const* d_in, const int* in_sizes, int n_in,
                              void* d_out, int out_size) {
    const float* Zela  = (const float*)d_in[0];   // Z_ELA
    const float* Ztopo = (const float*)d_in[1];   // Z_topo
    const float* Hinit = (const float*)d_in[2];   // H_initial
    float* out = (float*)d_out;

    float* hbuf = nullptr;
    cudaGetSymbolAddress((void**)&hbuf, g_Hbuf);

    float* buf[2] = { out, hbuf };

    init_kernel<<<256, 256>>>(Hinit, out);

    dim3 blk(32, 8);
    dim3 grdD((NM1 + 31) / 32, (NM1 + 7) / 8);
    dim3 grdU((N + 31) / 32, (N + 7) / 8);

    for (int s = 0; s < STEPS; s++) {
        diffus_kernel<<<grdD, blk>>>(buf[s & 1], Ztopo, s);
        update_kernel<<<grdU, blk>>>(buf[s & 1], buf[(s + 1) & 1], Ztopo, Zela, s);
    }
    // STEPS is even -> final H lands in buf[0] == d_out
}